// round 2
// baseline (speedup 1.0000x reference)
#include <cuda_runtime.h>
#include <stdint.h>

// NCA step: perceive (I, sobel-x, sobel-y per channel) -> 48->64 tanh -> 64->32 tanh
// -> 32->16 -> x + dx*mask.  B=16, H=W=256, C=16, NHWC fp32.
// Mask stored as 4-byte elements (bool upcast to float32 or int32) -> read uint32 != 0.

#define TW 16
#define TH 16
#define CH 16
#define HW 256
#define PITCH 17           // floats per pixel in smem tile (odd -> conflict-free)
#define ROWP (18 * PITCH)  // floats per tile row

__device__ __forceinline__ float tanh_fast(float v) {
    float y;
    asm("tanh.approx.f32 %0, %1;" : "=f"(y) : "f"(v));
    return y;
}

__global__ __launch_bounds__(256)
void nca_step_kernel(const float* __restrict__ x,
                     const float* __restrict__ w1, const float* __restrict__ b1,
                     const float* __restrict__ w2, const float* __restrict__ b2,
                     const float* __restrict__ w3, const float* __restrict__ b3,
                     const uint32_t* __restrict__ mask,
                     float* __restrict__ out)
{
    __shared__ float w1s[48 * 64];
    __shared__ float w2s[64 * 32];
    __shared__ float w3s[32 * 16];
    __shared__ float b1s[64];
    __shared__ float b2s[32];
    __shared__ float b3s[16];
    __shared__ float xs[18 * ROWP];   // 18x18 halo tile, 16ch @ pitch 17

    const int tid = threadIdx.x;

    // ---- stage weights ----
    for (int i = tid; i < 48 * 64; i += 256) w1s[i] = w1[i];
    for (int i = tid; i < 64 * 32; i += 256) w2s[i] = w2[i];
    for (int i = tid; i < 32 * 16; i += 256) w3s[i] = w3[i];
    if (tid < 64) b1s[tid] = b1[tid];
    else if (tid >= 64 && tid < 96) b2s[tid - 64] = b2[tid - 64];
    else if (tid >= 96 && tid < 112) b3s[tid - 96] = b3[tid - 96];

    const int bx = blockIdx.x, by = blockIdx.y, bb = blockIdx.z;
    const int gx0 = bx * TW - 1, gy0 = by * TH - 1;
    const float* xb = x + (size_t)bb * HW * HW * CH;

    // ---- stage x halo tile (zero pad outside image) ----
    for (int i = tid; i < 18 * 18 * 4; i += 256) {
        int q   = i & 3;
        int pix = i >> 2;
        int r   = pix / 18;
        int cc  = pix - r * 18;
        int gr = gy0 + r, gc = gx0 + cc;
        float4 v = make_float4(0.f, 0.f, 0.f, 0.f);
        if ((unsigned)gr < HW && (unsigned)gc < HW)
            v = *(const float4*)&xb[((size_t)gr * HW + gc) * CH + q * 4];
        float* dst = &xs[(r * 18 + cc) * PITCH + q * 4];
        dst[0] = v.x; dst[1] = v.y; dst[2] = v.z; dst[3] = v.w;
    }
    __syncthreads();

    const int lx = tid & 15, ly = tid >> 4;

    // ---- perceive fused with GEMM1: h1[64] = b1 + sum_c (I,gx,gy)_c . w1 ----
    float h1[64];
    #pragma unroll
    for (int d = 0; d < 64; d++) h1[d] = b1s[d];

    const float* p00 = &xs[((size_t)ly * 18 + lx) * PITCH];

    #pragma unroll 2
    for (int c = 0; c < CH; c++) {
        float v00 = p00[c],               v01 = p00[PITCH + c],           v02 = p00[2 * PITCH + c];
        float v10 = p00[ROWP + c],        v11 = p00[ROWP + PITCH + c],    v12 = p00[ROWP + 2 * PITCH + c];
        float v20 = p00[2 * ROWP + c],    v21 = p00[2 * ROWP + PITCH + c],v22 = p00[2 * ROWP + 2 * PITCH + c];
        float I  = v11;
        float gx = ((v02 - v00) + 2.f * (v12 - v10) + (v22 - v20)) * 0.125f;
        float gy = ((v20 - v00) + 2.f * (v21 - v01) + (v22 - v02)) * 0.125f;
        const float4* r0 = (const float4*)&w1s[(3 * c + 0) * 64];
        const float4* r1 = (const float4*)&w1s[(3 * c + 1) * 64];
        const float4* r2 = (const float4*)&w1s[(3 * c + 2) * 64];
        #pragma unroll
        for (int d4 = 0; d4 < 16; d4++) {
            float4 a = r0[d4], g = r1[d4], h = r2[d4];
            h1[d4 * 4 + 0] += I * a.x + gx * g.x + gy * h.x;
            h1[d4 * 4 + 1] += I * a.y + gx * g.y + gy * h.y;
            h1[d4 * 4 + 2] += I * a.z + gx * g.z + gy * h.z;
            h1[d4 * 4 + 3] += I * a.w + gx * g.w + gy * h.w;
        }
    }
    #pragma unroll
    for (int d = 0; d < 64; d++) h1[d] = tanh_fast(h1[d]);

    // ---- GEMM2: h2[32] = tanh(h1 . w2 + b2) ----
    float h2[32];
    #pragma unroll
    for (int d = 0; d < 32; d++) h2[d] = b2s[d];
    #pragma unroll 4
    for (int c = 0; c < 64; c++) {
        float hv = h1[c];
        const float4* wr = (const float4*)&w2s[c * 32];
        #pragma unroll
        for (int d4 = 0; d4 < 8; d4++) {
            float4 w = wr[d4];
            h2[d4 * 4 + 0] += hv * w.x;
            h2[d4 * 4 + 1] += hv * w.y;
            h2[d4 * 4 + 2] += hv * w.z;
            h2[d4 * 4 + 3] += hv * w.w;
        }
    }
    #pragma unroll
    for (int d = 0; d < 32; d++) h2[d] = tanh_fast(h2[d]);

    // ---- GEMM3: dv[16] = h2 . w3 + b3 ----
    float dv[16];
    #pragma unroll
    for (int d = 0; d < 16; d++) dv[d] = b3s[d];
    #pragma unroll 4
    for (int c = 0; c < 32; c++) {
        float hv = h2[c];
        const float4* wr = (const float4*)&w3s[c * 16];
        #pragma unroll
        for (int d4 = 0; d4 < 4; d4++) {
            float4 w = wr[d4];
            dv[d4 * 4 + 0] += hv * w.x;
            dv[d4 * 4 + 1] += hv * w.y;
            dv[d4 * 4 + 2] += hv * w.z;
            dv[d4 * 4 + 3] += hv * w.w;
        }
    }

    // ---- residual + mask, store ----
    const int px = bx * TW + lx, py = by * TH + ly;
    // mask elements are 4 bytes (bool upcast to f32 or i32): nonzero word == true
    float m = (mask[((size_t)bb * HW + py) * HW + px] != 0u) ? 1.f : 0.f;
    const float* ctr = &xs[((size_t)(ly + 1) * 18 + (lx + 1)) * PITCH];
    float* o = out + (((size_t)bb * HW + py) * HW + px) * CH;
    #pragma unroll
    for (int d4 = 0; d4 < 4; d4++) {
        float4 r;
        r.x = ctr[d4 * 4 + 0] + dv[d4 * 4 + 0] * m;
        r.y = ctr[d4 * 4 + 1] + dv[d4 * 4 + 1] * m;
        r.z = ctr[d4 * 4 + 2] + dv[d4 * 4 + 2] * m;
        r.w = ctr[d4 * 4 + 3] + dv[d4 * 4 + 3] * m;
        *(float4*)&o[d4 * 4] = r;
    }
}

extern "C" void kernel_launch(void* const* d_in, const int* in_sizes, int n_in,
                              void* d_out, int out_size)
{
    const float* x  = (const float*)d_in[0];
    const float* w1 = (const float*)d_in[1];
    const float* b1 = (const float*)d_in[2];
    const float* w2 = (const float*)d_in[3];
    const float* b2 = (const float*)d_in[4];
    const float* w3 = (const float*)d_in[5];
    const float* b3 = (const float*)d_in[6];
    const uint32_t* mask = (const uint32_t*)d_in[7];
    float* out = (float*)d_out;

    dim3 grid(HW / TW, HW / TH, 16);
    nca_step_kernel<<<grid, 256>>>(x, w1, b1, w2, b2, w3, b3, mask, out);
}

// round 4
// speedup vs baseline: 1.8397x; 1.8397x over previous
#include <cuda_runtime.h>
#include <stdint.h>

// NCA step, register-tiled, NO smem aliasing.
// CTA = 256 threads, 16x16 px tile. ys/h1s/h2s stored [feature][pixel] (pitch 260).
// GEMM A-loads are warp-contiguous float4 (conflict-free); B-loads warp-uniform.

#define HW   256
#define CH   16
#define YP   260      // pixel pitch for ys/h1s/h2s rows
#define XCS  340      // channel stride for halo xs[16][18*18]
#define DVP  17       // pixel pitch for dvs

#define OFF_YS   0
#define OFF_H1S  12480
#define OFF_H2S  29120
#define OFF_DVS  37440
#define OFF_XS   41792
#define OFF_W1   47232
#define OFF_W2   50304
#define OFF_W3   52352
#define OFF_B1   52864
#define OFF_B2   52928
#define OFF_B3   52960
#define OFF_MS   52992
#define SMEM_FLOATS 53248
#define SMEM_BYTES  (SMEM_FLOATS * 4)

static_assert(OFF_H1S == OFF_YS + 48 * YP, "ys");
static_assert(OFF_H2S == OFF_H1S + 64 * YP, "h1s");
static_assert(OFF_DVS == OFF_H2S + 32 * YP, "h2s");
static_assert(OFF_XS  == OFF_DVS + 256 * DVP, "dvs");
static_assert(OFF_W1  == OFF_XS + 16 * XCS, "xs");
static_assert(OFF_W2  == OFF_W1 + 48 * 64, "w1");
static_assert(OFF_W3  == OFF_W2 + 64 * 32, "w2");
static_assert(OFF_B1  == OFF_W3 + 32 * 16, "w3");
static_assert(OFF_MS + 256 == SMEM_FLOATS, "total");
static_assert(SMEM_BYTES <= 227 * 1024, "smem limit");

__device__ __forceinline__ float tanh_fast(float v) {
    float y;
    asm("tanh.approx.f32 %0, %1;" : "=f"(y) : "f"(v));
    return y;
}

__global__ __launch_bounds__(256, 1)
void nca_step_kernel(const float* __restrict__ x,
                     const float* __restrict__ w1, const float* __restrict__ b1,
                     const float* __restrict__ w2, const float* __restrict__ b2,
                     const float* __restrict__ w3, const float* __restrict__ b3,
                     const uint32_t* __restrict__ mask,
                     float* __restrict__ out)
{
    extern __shared__ float sm[];
    float* ys  = sm + OFF_YS;
    float* h1s = sm + OFF_H1S;
    float* h2s = sm + OFF_H2S;
    float* dvs = sm + OFF_DVS;
    float* xs  = sm + OFF_XS;
    float* w1s = sm + OFF_W1;
    float* w2s = sm + OFF_W2;
    float* w3s = sm + OFF_W3;
    float* b1s = sm + OFF_B1;
    float* b2s = sm + OFF_B2;
    float* b3s = sm + OFF_B3;
    float* ms  = sm + OFF_MS;

    const int tid = threadIdx.x;
    const int bx = blockIdx.x, by = blockIdx.y, bb = blockIdx.z;
    const int y0 = by * 16, x0 = bx * 16;

    // ---------------- phase 0: stage weights / biases / mask / halo ----------------
    for (int i = tid; i < 48 * 64; i += 256) w1s[i] = w1[i];
    for (int i = tid; i < 64 * 32; i += 256) w2s[i] = w2[i];
    for (int i = tid; i < 32 * 16; i += 256) w3s[i] = w3[i];
    if (tid < 64)       b1s[tid] = b1[tid];
    else if (tid < 96)  b2s[tid - 64] = b2[tid - 64];
    else if (tid < 112) b3s[tid - 96] = b3[tid - 96];

    {
        int py = tid >> 4, xx = tid & 15;
        uint32_t w = mask[((size_t)bb * HW + (y0 + py)) * HW + (x0 + xx)];
        ms[tid] = (w != 0u) ? 1.f : 0.f;
    }

    {   // halo tile, channel-major xs[c][r*18+cc], zero-pad outside image
        const float* xb = x + (size_t)bb * HW * HW * CH;
        const int gy0 = y0 - 1, gx0 = x0 - 1;
        for (int i = tid; i < 18 * 18 * 4; i += 256) {
            int q = i & 3, pix = i >> 2;
            int r = pix / 18, cc = pix - r * 18;
            int gr = gy0 + r, gc = gx0 + cc;
            float4 v = make_float4(0.f, 0.f, 0.f, 0.f);
            if ((unsigned)gr < HW && (unsigned)gc < HW)
                v = *(const float4*)&xb[((size_t)gr * HW + gc) * CH + q * 4];
            int base = r * 18 + cc;
            xs[(4 * q + 0) * XCS + base] = v.x;
            xs[(4 * q + 1) * XCS + base] = v.y;
            xs[(4 * q + 2) * XCS + base] = v.z;
            xs[(4 * q + 3) * XCS + base] = v.w;
        }
    }
    __syncthreads();

    // ---------------- phase 1: stencil -> ys[48][256] ----------------
    {
        const int c = tid >> 4, xx = tid & 15;
        const float* xc = xs + c * XCS;
        float r0a = xc[xx],      r0b = xc[xx + 1],      r0c = xc[xx + 2];
        float r1a = xc[18 + xx], r1b = xc[18 + xx + 1], r1c = xc[18 + xx + 2];
        float* yI = ys + (3 * c + 0) * YP;
        float* yX = ys + (3 * c + 1) * YP;
        float* yY = ys + (3 * c + 2) * YP;
        #pragma unroll
        for (int py = 0; py < 16; py++) {
            const float* row2 = xc + (py + 2) * 18 + xx;
            float r2a = row2[0], r2b = row2[1], r2c = row2[2];
            float gx = ((r0c - r0a) + 2.f * (r1c - r1a) + (r2c - r2a)) * 0.125f;
            float gy = ((r2a - r0a) + 2.f * (r2b - r0b) + (r2c - r0c)) * 0.125f;
            int p = py * 16 + xx;
            yI[p] = r1b;
            yX[p] = gx;
            yY[p] = gy;
            r0a = r1a; r0b = r1b; r0c = r1c;
            r1a = r2a; r1b = r2b; r1c = r2c;
        }
    }
    __syncthreads();

    // thread -> (lane pixels, d-group): pixels {lane*4..+3} and {128+lane*4..+3}
    const int lane = tid & 31, td = tid >> 5;
    const int pA = lane * 4, pB = 128 + lane * 4;

    // ---------------- phase 2: GEMM1 [256x64] = ys @ w1, tanh -> h1s ----------------
    {
        const int d0 = td * 8;
        float accA[4][8], accB[4][8];
        #pragma unroll
        for (int i = 0; i < 4; i++)
            #pragma unroll
            for (int j = 0; j < 8; j++) { accA[i][j] = b1s[d0 + j]; accB[i][j] = b1s[d0 + j]; }

        #pragma unroll 4
        for (int k = 0; k < 48; k++) {
            float4 aA = *(const float4*)&ys[k * YP + pA];
            float4 aB = *(const float4*)&ys[k * YP + pB];
            float4 wL = *(const float4*)&w1s[k * 64 + d0];
            float4 wH = *(const float4*)&w1s[k * 64 + d0 + 4];
            float wv[8] = {wL.x, wL.y, wL.z, wL.w, wH.x, wH.y, wH.z, wH.w};
            float av[4] = {aA.x, aA.y, aA.z, aA.w};
            float bv[4] = {aB.x, aB.y, aB.z, aB.w};
            #pragma unroll
            for (int i = 0; i < 4; i++)
                #pragma unroll
                for (int j = 0; j < 8; j++) {
                    accA[i][j] += av[i] * wv[j];
                    accB[i][j] += bv[i] * wv[j];
                }
        }
        #pragma unroll
        for (int j = 0; j < 8; j++) {
            float4 vA, vB;
            vA.x = tanh_fast(accA[0][j]); vA.y = tanh_fast(accA[1][j]);
            vA.z = tanh_fast(accA[2][j]); vA.w = tanh_fast(accA[3][j]);
            vB.x = tanh_fast(accB[0][j]); vB.y = tanh_fast(accB[1][j]);
            vB.z = tanh_fast(accB[2][j]); vB.w = tanh_fast(accB[3][j]);
            *(float4*)&h1s[(d0 + j) * YP + pA] = vA;
            *(float4*)&h1s[(d0 + j) * YP + pB] = vB;
        }
    }
    __syncthreads();

    // ---------------- phase 3: GEMM2 [256x32] = h1 @ w2, tanh -> h2s ----------------
    {
        const int d0 = td * 4;
        float accA[4][4], accB[4][4];
        #pragma unroll
        for (int i = 0; i < 4; i++)
            #pragma unroll
            for (int j = 0; j < 4; j++) { accA[i][j] = b2s[d0 + j]; accB[i][j] = b2s[d0 + j]; }

        #pragma unroll 4
        for (int k = 0; k < 64; k++) {
            float4 aA = *(const float4*)&h1s[k * YP + pA];
            float4 aB = *(const float4*)&h1s[k * YP + pB];
            float4 w = *(const float4*)&w2s[k * 32 + d0];
            float wv[4] = {w.x, w.y, w.z, w.w};
            float av[4] = {aA.x, aA.y, aA.z, aA.w};
            float bv[4] = {aB.x, aB.y, aB.z, aB.w};
            #pragma unroll
            for (int i = 0; i < 4; i++)
                #pragma unroll
                for (int j = 0; j < 4; j++) {
                    accA[i][j] += av[i] * wv[j];
                    accB[i][j] += bv[i] * wv[j];
                }
        }
        #pragma unroll
        for (int j = 0; j < 4; j++) {
            float4 vA, vB;
            vA.x = tanh_fast(accA[0][j]); vA.y = tanh_fast(accA[1][j]);
            vA.z = tanh_fast(accA[2][j]); vA.w = tanh_fast(accA[3][j]);
            vB.x = tanh_fast(accB[0][j]); vB.y = tanh_fast(accB[1][j]);
            vB.z = tanh_fast(accB[2][j]); vB.w = tanh_fast(accB[3][j]);
            *(float4*)&h2s[(d0 + j) * YP + pA] = vA;
            *(float4*)&h2s[(d0 + j) * YP + pB] = vB;
        }
    }
    __syncthreads();

    // ---------------- phase 4: GEMM3 [256x16] = h2 @ w3 -> dvs ----------------
    {
        float acc[16];
        #pragma unroll
        for (int c = 0; c < 16; c++) acc[c] = b3s[c];
        #pragma unroll 4
        for (int k = 0; k < 32; k++) {
            float av = h2s[k * YP + tid];
            const float4* wr = (const float4*)&w3s[k * 16];
            #pragma unroll
            for (int c4 = 0; c4 < 4; c4++) {
                float4 w = wr[c4];
                acc[c4 * 4 + 0] += av * w.x;
                acc[c4 * 4 + 1] += av * w.y;
                acc[c4 * 4 + 2] += av * w.z;
                acc[c4 * 4 + 3] += av * w.w;
            }
        }
        float* d = dvs + tid * DVP;
        #pragma unroll
        for (int c = 0; c < 16; c++) d[c] = acc[c];
    }
    __syncthreads();

    // ---------------- phase 5: out = x + dv*mask (center x from smem halo) ----------------
    {
        const int py = tid >> 4, xx = tid & 15;
        const float m = ms[tid];
        const float* d = dvs + tid * DVP;
        const int hbase = (py + 1) * 18 + (xx + 1);
        float* o = out + (((size_t)bb * HW + (y0 + py)) * HW + (x0 + xx)) * CH;
        #pragma unroll
        for (int c4 = 0; c4 < 4; c4++) {
            float4 r;
            r.x = xs[(c4 * 4 + 0) * XCS + hbase] + d[c4 * 4 + 0] * m;
            r.y = xs[(c4 * 4 + 1) * XCS + hbase] + d[c4 * 4 + 1] * m;
            r.z = xs[(c4 * 4 + 2) * XCS + hbase] + d[c4 * 4 + 2] * m;
            r.w = xs[(c4 * 4 + 3) * XCS + hbase] + d[c4 * 4 + 3] * m;
            *(float4*)&o[c4 * 4] = r;
        }
    }
}

extern "C" void kernel_launch(void* const* d_in, const int* in_sizes, int n_in,
                              void* d_out, int out_size)
{
    const float* x  = (const float*)d_in[0];
    const float* w1 = (const float*)d_in[1];
    const float* b1 = (const float*)d_in[2];
    const float* w2 = (const float*)d_in[3];
    const float* b2 = (const float*)d_in[4];
    const float* w3 = (const float*)d_in[5];
    const float* b3 = (const float*)d_in[6];
    const uint32_t* mask = (const uint32_t*)d_in[7];
    float* out = (float*)d_out;

    cudaFuncSetAttribute(nca_step_kernel,
                         cudaFuncAttributeMaxDynamicSharedMemorySize, SMEM_BYTES);
    dim3 grid(HW / 16, HW / 16, 16);
    nca_step_kernel<<<grid, 256, SMEM_BYTES>>>(x, w1, b1, w2, b2, w3, b3, mask, out);
}

// round 5
// speedup vs baseline: 2.2345x; 1.2146x over previous
#include <cuda_runtime.h>
#include <stdint.h>

// NCA step, register-tiled, 16x8 px tile, 256 threads, 2 CTAs/SM (111 KB smem).
// GEMM3 fused with epilogue (no dvs buffer).

#define HW   256
#define CH   16
#define TW   16
#define TH   8
#define NPIX 128
#define YP   132      // pixel pitch for ys/h1s/h2s rows
#define XCS  184      // channel stride for halo xs[16][10*18]

#define OFF_YS   0
#define OFF_H1S  6336
#define OFF_H2S  14784
#define OFF_XS   19008
#define OFF_W1   21952
#define OFF_W2   25024
#define OFF_W3   27072
#define OFF_B1   27584
#define OFF_B2   27648
#define OFF_B3   27680
#define OFF_MS   27696
#define SMEM_FLOATS 27824
#define SMEM_BYTES  (SMEM_FLOATS * 4)

static_assert(OFF_H1S == OFF_YS + 48 * YP, "ys");
static_assert(OFF_H2S == OFF_H1S + 64 * YP, "h1s");
static_assert(OFF_XS  == OFF_H2S + 32 * YP, "h2s");
static_assert(OFF_W1  == OFF_XS + 16 * XCS, "xs");
static_assert(OFF_W2  == OFF_W1 + 48 * 64, "w1");
static_assert(OFF_W3  == OFF_W2 + 64 * 32, "w2");
static_assert(OFF_B1  == OFF_W3 + 32 * 16, "w3");
static_assert(OFF_MS + NPIX == SMEM_FLOATS, "total");
static_assert(2 * SMEM_BYTES <= 227 * 1024, "2 CTA/SM");

__device__ __forceinline__ float tanh_fast(float v) {
    float y;
    asm("tanh.approx.f32 %0, %1;" : "=f"(y) : "f"(v));
    return y;
}

__global__ __launch_bounds__(256, 2)
void nca_step_kernel(const float* __restrict__ x,
                     const float* __restrict__ w1, const float* __restrict__ b1,
                     const float* __restrict__ w2, const float* __restrict__ b2,
                     const float* __restrict__ w3, const float* __restrict__ b3,
                     const uint32_t* __restrict__ mask,
                     float* __restrict__ out)
{
    extern __shared__ float sm[];
    float* ys  = sm + OFF_YS;
    float* h1s = sm + OFF_H1S;
    float* h2s = sm + OFF_H2S;
    float* xs  = sm + OFF_XS;
    float* w1s = sm + OFF_W1;
    float* w2s = sm + OFF_W2;
    float* w3s = sm + OFF_W3;
    float* b1s = sm + OFF_B1;
    float* b2s = sm + OFF_B2;
    float* b3s = sm + OFF_B3;
    float* ms  = sm + OFF_MS;

    const int tid = threadIdx.x;
    const int bx = blockIdx.x, by = blockIdx.y, bb = blockIdx.z;
    const int y0 = by * TH, x0 = bx * TW;

    // ---------------- phase 0: stage weights / biases / mask / halo ----------------
    for (int i = tid; i < 48 * 64; i += 256) w1s[i] = w1[i];
    for (int i = tid; i < 64 * 32; i += 256) w2s[i] = w2[i];
    for (int i = tid; i < 32 * 16; i += 256) w3s[i] = w3[i];
    if (tid < 64)       b1s[tid] = b1[tid];
    else if (tid < 96)  b2s[tid - 64] = b2[tid - 64];
    else if (tid < 112) b3s[tid - 96] = b3[tid - 96];

    if (tid < NPIX) {
        int py = tid >> 4, xx = tid & 15;
        uint32_t w = mask[((size_t)bb * HW + (y0 + py)) * HW + (x0 + xx)];
        ms[tid] = (w != 0u) ? 1.f : 0.f;
    }

    {   // halo 10 rows x 18 cols, channel-major xs[c][r*18+cc], zero-pad outside
        const float* xb = x + (size_t)bb * HW * HW * CH;
        const int gy0 = y0 - 1, gx0 = x0 - 1;
        for (int i = tid; i < 10 * 18 * 4; i += 256) {
            int q = i & 3, pix = i >> 2;
            int r = pix / 18, cc = pix - r * 18;
            int gr = gy0 + r, gc = gx0 + cc;
            float4 v = make_float4(0.f, 0.f, 0.f, 0.f);
            if ((unsigned)gr < HW && (unsigned)gc < HW)
                v = *(const float4*)&xb[((size_t)gr * HW + gc) * CH + q * 4];
            int base = r * 18 + cc;
            xs[(4 * q + 0) * XCS + base] = v.x;
            xs[(4 * q + 1) * XCS + base] = v.y;
            xs[(4 * q + 2) * XCS + base] = v.z;
            xs[(4 * q + 3) * XCS + base] = v.w;
        }
    }
    __syncthreads();

    // ---------------- phase 1: stencil -> ys[48][128] ----------------
    {
        const int c = tid >> 4, xx = tid & 15;
        const float* xc = xs + c * XCS;
        float r0a = xc[xx],      r0b = xc[xx + 1],      r0c = xc[xx + 2];
        float r1a = xc[18 + xx], r1b = xc[18 + xx + 1], r1c = xc[18 + xx + 2];
        float* yI = ys + (3 * c + 0) * YP;
        float* yX = ys + (3 * c + 1) * YP;
        float* yY = ys + (3 * c + 2) * YP;
        #pragma unroll
        for (int py = 0; py < TH; py++) {
            const float* row2 = xc + (py + 2) * 18 + xx;
            float r2a = row2[0], r2b = row2[1], r2c = row2[2];
            float gx = ((r0c - r0a) + 2.f * (r1c - r1a) + (r2c - r2a)) * 0.125f;
            float gy = ((r2a - r0a) + 2.f * (r2b - r0b) + (r2c - r0c)) * 0.125f;
            int p = py * 16 + xx;
            yI[p] = r1b;
            yX[p] = gx;
            yY[p] = gy;
            r0a = r1a; r0b = r1b; r0c = r1c;
            r1a = r2a; r1b = r2b; r1c = r2c;
        }
    }
    __syncthreads();

    const int lane = tid & 31, td = tid >> 5;
    const int pA = lane * 4;    // 4 px per thread, warp-contiguous float4

    // ---------------- phase 2: GEMM1 [128x64] = ys @ w1, tanh -> h1s ----------------
    {
        const int d0 = td * 8;
        float acc[4][8];
        #pragma unroll
        for (int i = 0; i < 4; i++)
            #pragma unroll
            for (int j = 0; j < 8; j++) acc[i][j] = b1s[d0 + j];

        #pragma unroll 4
        for (int k = 0; k < 48; k++) {
            float4 aA = *(const float4*)&ys[k * YP + pA];
            float4 wL = *(const float4*)&w1s[k * 64 + d0];
            float4 wH = *(const float4*)&w1s[k * 64 + d0 + 4];
            float wv[8] = {wL.x, wL.y, wL.z, wL.w, wH.x, wH.y, wH.z, wH.w};
            float av[4] = {aA.x, aA.y, aA.z, aA.w};
            #pragma unroll
            for (int i = 0; i < 4; i++)
                #pragma unroll
                for (int j = 0; j < 8; j++)
                    acc[i][j] += av[i] * wv[j];
        }
        #pragma unroll
        for (int j = 0; j < 8; j++) {
            float4 v;
            v.x = tanh_fast(acc[0][j]); v.y = tanh_fast(acc[1][j]);
            v.z = tanh_fast(acc[2][j]); v.w = tanh_fast(acc[3][j]);
            *(float4*)&h1s[(d0 + j) * YP + pA] = v;
        }
    }
    __syncthreads();

    // ---------------- phase 3: GEMM2 [128x32] = h1 @ w2, tanh -> h2s ----------------
    {
        const int d0 = td * 4;
        float acc[4][4];
        #pragma unroll
        for (int i = 0; i < 4; i++)
            #pragma unroll
            for (int j = 0; j < 4; j++) acc[i][j] = b2s[d0 + j];

        #pragma unroll 8
        for (int k = 0; k < 64; k++) {
            float4 aA = *(const float4*)&h1s[k * YP + pA];
            float4 w = *(const float4*)&w2s[k * 32 + d0];
            float wv[4] = {w.x, w.y, w.z, w.w};
            float av[4] = {aA.x, aA.y, aA.z, aA.w};
            #pragma unroll
            for (int i = 0; i < 4; i++)
                #pragma unroll
                for (int j = 0; j < 4; j++)
                    acc[i][j] += av[i] * wv[j];
        }
        #pragma unroll
        for (int j = 0; j < 4; j++) {
            float4 v;
            v.x = tanh_fast(acc[0][j]); v.y = tanh_fast(acc[1][j]);
            v.z = tanh_fast(acc[2][j]); v.w = tanh_fast(acc[3][j]);
            *(float4*)&h2s[(d0 + j) * YP + pA] = v;
        }
    }
    __syncthreads();

    // ---------------- phase 4: GEMM3 [128x16] + epilogue (fused, no dvs) ----------------
    {
        const int px = tid >> 1;          // 0..127
        const int c0 = (tid & 1) * 8;     // channel half
        float acc[8];
        #pragma unroll
        for (int j = 0; j < 8; j++) acc[j] = b3s[c0 + j];

        #pragma unroll 8
        for (int k = 0; k < 32; k++) {
            float av = h2s[k * YP + px];
            float4 wA = *(const float4*)&w3s[k * 16 + c0];
            float4 wB = *(const float4*)&w3s[k * 16 + c0 + 4];
            acc[0] += av * wA.x; acc[1] += av * wA.y;
            acc[2] += av * wA.z; acc[3] += av * wA.w;
            acc[4] += av * wB.x; acc[5] += av * wB.y;
            acc[6] += av * wB.z; acc[7] += av * wB.w;
        }

        const int py = px >> 4, xx = px & 15;
        const float m = ms[px];
        const int hbase = (py + 1) * 18 + (xx + 1);
        float* o = out + (((size_t)bb * HW + (y0 + py)) * HW + (x0 + xx)) * CH + c0;
        float4 r0, r1;
        r0.x = xs[(c0 + 0) * XCS + hbase] + acc[0] * m;
        r0.y = xs[(c0 + 1) * XCS + hbase] + acc[1] * m;
        r0.z = xs[(c0 + 2) * XCS + hbase] + acc[2] * m;
        r0.w = xs[(c0 + 3) * XCS + hbase] + acc[3] * m;
        r1.x = xs[(c0 + 4) * XCS + hbase] + acc[4] * m;
        r1.y = xs[(c0 + 5) * XCS + hbase] + acc[5] * m;
        r1.z = xs[(c0 + 6) * XCS + hbase] + acc[6] * m;
        r1.w = xs[(c0 + 7) * XCS + hbase] + acc[7] * m;
        *(float4*)&o[0] = r0;
        *(float4*)&o[4] = r1;
    }
}

extern "C" void kernel_launch(void* const* d_in, const int* in_sizes, int n_in,
                              void* d_out, int out_size)
{
    const float* x  = (const float*)d_in[0];
    const float* w1 = (const float*)d_in[1];
    const float* b1 = (const float*)d_in[2];
    const float* w2 = (const float*)d_in[3];
    const float* b2 = (const float*)d_in[4];
    const float* w3 = (const float*)d_in[5];
    const float* b3 = (const float*)d_in[6];
    const uint32_t* mask = (const uint32_t*)d_in[7];
    float* out = (float*)d_out;

    cudaFuncSetAttribute(nca_step_kernel,
                         cudaFuncAttributeMaxDynamicSharedMemorySize, SMEM_BYTES);
    dim3 grid(HW / TW, HW / TH, 16);
    nca_step_kernel<<<grid, 256, SMEM_BYTES>>>(x, w1, b1, w2, b2, w3, b3, mask, out);
}

// round 6
// speedup vs baseline: 4.2069x; 1.8827x over previous
#include <cuda_runtime.h>
#include <stdint.h>

// NCA step via tf32 mma.sync.m16n8k8.
// CTA = 256 thr (8 warps), 16x8 px tile. Activations stored [feature][px] pitch 136
// (tf32-rounded) = col-major B operand. Weights = A fragments loaded from gmem (L2).
// D[d][px] layout of each GEMM output == B layout of the next GEMM.

#define HW   256
#define CH   16
#define TW   16
#define TH   8
#define NPIX 128
#define YP   136      // pitch: 136 mod 32 == 8 -> B-fragment LDS conflict-free
#define XCS  184      // halo channel stride xs[16][10*18]
#define DP   20       // dxT pixel pitch

#define OFF_YS   0
#define OFF_H1S  6528
#define OFF_H2S  15232
#define OFF_DXT  19584
#define OFF_XS   22144
#define OFF_B1   25088
#define OFF_B2   25152
#define OFF_B3   25184
#define OFF_MS   25200
#define SMEM_FLOATS 25328
#define SMEM_BYTES  (SMEM_FLOATS * 4)

static_assert(OFF_H1S == OFF_YS  + 48 * YP, "ys");
static_assert(OFF_H2S == OFF_H1S + 64 * YP, "h1s");
static_assert(OFF_DXT == OFF_H2S + 32 * YP, "h2s");
static_assert(OFF_XS  == OFF_DXT + 128 * DP, "dxT");
static_assert(OFF_B1  == OFF_XS  + 16 * XCS, "xs");
static_assert(OFF_MS + NPIX == SMEM_FLOATS, "total");
static_assert(2 * SMEM_BYTES <= 227 * 1024, "2 CTA/SM");

__device__ __forceinline__ float tanh_fast(float v) {
    float y;
    asm("tanh.approx.f32 %0, %1;" : "=f"(y) : "f"(v));
    return y;
}
__device__ __forceinline__ uint32_t f2tf(float f) {
    uint32_t u;
    asm("cvt.rna.tf32.f32 %0, %1;" : "=r"(u) : "f"(f));
    return u;
}
__device__ __forceinline__ float f2tff(float f) { return __uint_as_float(f2tf(f)); }

__device__ __forceinline__ void mma_tf32(float& c0, float& c1, float& c2, float& c3,
                                         uint32_t a0, uint32_t a1, uint32_t a2, uint32_t a3,
                                         uint32_t b0, uint32_t b1)
{
    asm volatile(
        "mma.sync.aligned.m16n8k8.row.col.f32.tf32.tf32.f32 "
        "{%0,%1,%2,%3},{%4,%5,%6,%7},{%8,%9},{%0,%1,%2,%3};"
        : "+f"(c0), "+f"(c1), "+f"(c2), "+f"(c3)
        : "r"(a0), "r"(a1), "r"(a2), "r"(a3), "r"(b0), "r"(b1));
}

__global__ __launch_bounds__(256, 2)
void nca_step_kernel(const float* __restrict__ x,
                     const float* __restrict__ w1, const float* __restrict__ b1,
                     const float* __restrict__ w2, const float* __restrict__ b2,
                     const float* __restrict__ w3, const float* __restrict__ b3,
                     const uint32_t* __restrict__ mask,
                     float* __restrict__ out)
{
    extern __shared__ float sm[];
    float* ys  = sm + OFF_YS;
    float* h1s = sm + OFF_H1S;
    float* h2s = sm + OFF_H2S;
    float* dxT = sm + OFF_DXT;
    float* xs  = sm + OFF_XS;
    float* b1s = sm + OFF_B1;
    float* b2s = sm + OFF_B2;
    float* b3s = sm + OFF_B3;
    float* ms  = sm + OFF_MS;

    const int tid = threadIdx.x;
    const int bx = blockIdx.x, by = blockIdx.y, bb = blockIdx.z;
    const int y0 = by * TH, x0 = bx * TW;

    // ---------------- phase 0: biases / mask / halo ----------------
    if (tid < 64)       b1s[tid] = b1[tid];
    else if (tid < 96)  b2s[tid - 64] = b2[tid - 64];
    else if (tid < 112) b3s[tid - 96] = b3[tid - 96];

    if (tid < NPIX) {
        int py = tid >> 4, xx = tid & 15;
        uint32_t w = mask[((size_t)bb * HW + (y0 + py)) * HW + (x0 + xx)];
        ms[tid] = (w != 0u) ? 1.f : 0.f;
    }

    {   // halo 10x18, channel-major, zero-pad outside image
        const float* xb = x + (size_t)bb * HW * HW * CH;
        const int gy0 = y0 - 1, gx0 = x0 - 1;
        for (int i = tid; i < 10 * 18 * 4; i += 256) {
            int q = i & 3, pix = i >> 2;
            int r = pix / 18, cc = pix - r * 18;
            int gr = gy0 + r, gc = gx0 + cc;
            float4 v = make_float4(0.f, 0.f, 0.f, 0.f);
            if ((unsigned)gr < HW && (unsigned)gc < HW)
                v = *(const float4*)&xb[((size_t)gr * HW + gc) * CH + q * 4];
            int base = r * 18 + cc;
            xs[(4 * q + 0) * XCS + base] = v.x;
            xs[(4 * q + 1) * XCS + base] = v.y;
            xs[(4 * q + 2) * XCS + base] = v.z;
            xs[(4 * q + 3) * XCS + base] = v.w;
        }
    }
    __syncthreads();

    // ---------------- phase 1: stencil -> ys[48][128] (tf32-rounded) ----------------
    {
        const int c = tid >> 4, xx = tid & 15;
        const float* xc = xs + c * XCS;
        float r0a = xc[xx],      r0b = xc[xx + 1],      r0c = xc[xx + 2];
        float r1a = xc[18 + xx], r1b = xc[18 + xx + 1], r1c = xc[18 + xx + 2];
        float* yI = ys + (3 * c + 0) * YP;
        float* yX = ys + (3 * c + 1) * YP;
        float* yY = ys + (3 * c + 2) * YP;
        #pragma unroll
        for (int py = 0; py < TH; py++) {
            const float* row2 = xc + (py + 2) * 18 + xx;
            float r2a = row2[0], r2b = row2[1], r2c = row2[2];
            float gx = ((r0c - r0a) + 2.f * (r1c - r1a) + (r2c - r2a)) * 0.125f;
            float gy = ((r2a - r0a) + 2.f * (r2b - r0b) + (r2c - r0c)) * 0.125f;
            int p = py * 16 + xx;
            yI[p] = f2tff(r1b);
            yX[p] = f2tff(gx);
            yY[p] = f2tff(gy);
            r0a = r1a; r0b = r1b; r0c = r1c;
            r1a = r2a; r1b = r2b; r1c = r2c;
        }
    }
    __syncthreads();

    const int lane = tid & 31, warp = tid >> 5;
    const int g = lane >> 2, t = lane & 3;

    // ---------------- phase 2: GEMM1 h1[64][128] = tanh(W1^T @ ys + b1) ----------------
    {
        const int d0 = (warp & 3) * 16;
        const int pb = (warp >> 2) * 64;
        uint32_t A[6][4];
        #pragma unroll
        for (int kt = 0; kt < 6; kt++) {
            int k0 = kt * 8;
            A[kt][0] = f2tf(w1[(k0 + t) * 64 + d0 + g]);
            A[kt][1] = f2tf(w1[(k0 + t) * 64 + d0 + g + 8]);
            A[kt][2] = f2tf(w1[(k0 + t + 4) * 64 + d0 + g]);
            A[kt][3] = f2tf(w1[(k0 + t + 4) * 64 + d0 + g + 8]);
        }
        const float bl = b1s[d0 + g], bh = b1s[d0 + g + 8];
        #pragma unroll
        for (int nt = 0; nt < 8; nt++) {
            const int px0 = pb + nt * 8;
            float c0 = bl, c1 = bl, c2 = bh, c3 = bh;
            #pragma unroll
            for (int kt = 0; kt < 6; kt++) {
                int k0 = kt * 8;
                uint32_t bv0 = __float_as_uint(ys[(k0 + t) * YP + px0 + g]);
                uint32_t bv1 = __float_as_uint(ys[(k0 + t + 4) * YP + px0 + g]);
                mma_tf32(c0, c1, c2, c3, A[kt][0], A[kt][1], A[kt][2], A[kt][3], bv0, bv1);
            }
            float2 lo = make_float2(f2tff(tanh_fast(c0)), f2tff(tanh_fast(c1)));
            float2 hi = make_float2(f2tff(tanh_fast(c2)), f2tff(tanh_fast(c3)));
            *(float2*)&h1s[(d0 + g) * YP + px0 + 2 * t]     = lo;
            *(float2*)&h1s[(d0 + g + 8) * YP + px0 + 2 * t] = hi;
        }
    }
    __syncthreads();

    // ---------------- phase 3: GEMM2 h2[32][128] = tanh(W2^T @ h1 + b2) ----------------
    {
        const int d0 = (warp & 1) * 16;
        const int pb = (warp >> 1) * 32;
        uint32_t A[8][4];
        #pragma unroll
        for (int kt = 0; kt < 8; kt++) {
            int k0 = kt * 8;
            A[kt][0] = f2tf(w2[(k0 + t) * 32 + d0 + g]);
            A[kt][1] = f2tf(w2[(k0 + t) * 32 + d0 + g + 8]);
            A[kt][2] = f2tf(w2[(k0 + t + 4) * 32 + d0 + g]);
            A[kt][3] = f2tf(w2[(k0 + t + 4) * 32 + d0 + g + 8]);
        }
        const float bl = b2s[d0 + g], bh = b2s[d0 + g + 8];
        #pragma unroll
        for (int nt = 0; nt < 4; nt++) {
            const int px0 = pb + nt * 8;
            float c0 = bl, c1 = bl, c2 = bh, c3 = bh;
            #pragma unroll
            for (int kt = 0; kt < 8; kt++) {
                int k0 = kt * 8;
                uint32_t bv0 = __float_as_uint(h1s[(k0 + t) * YP + px0 + g]);
                uint32_t bv1 = __float_as_uint(h1s[(k0 + t + 4) * YP + px0 + g]);
                mma_tf32(c0, c1, c2, c3, A[kt][0], A[kt][1], A[kt][2], A[kt][3], bv0, bv1);
            }
            float2 lo = make_float2(f2tff(tanh_fast(c0)), f2tff(tanh_fast(c1)));
            float2 hi = make_float2(f2tff(tanh_fast(c2)), f2tff(tanh_fast(c3)));
            *(float2*)&h2s[(d0 + g) * YP + px0 + 2 * t]     = lo;
            *(float2*)&h2s[(d0 + g + 8) * YP + px0 + 2 * t] = hi;
        }
    }
    __syncthreads();

    // ---------------- phase 4: GEMM3 dx[16][128] = W3^T @ h2 + b3 -> dxT[px][d] ----------------
    {
        const int pb = warp * 16;
        uint32_t A[4][4];
        #pragma unroll
        for (int kt = 0; kt < 4; kt++) {
            int k0 = kt * 8;
            A[kt][0] = f2tf(w3[(k0 + t) * 16 + g]);
            A[kt][1] = f2tf(w3[(k0 + t) * 16 + g + 8]);
            A[kt][2] = f2tf(w3[(k0 + t + 4) * 16 + g]);
            A[kt][3] = f2tf(w3[(k0 + t + 4) * 16 + g + 8]);
        }
        const float bl = b3s[g], bh = b3s[g + 8];
        #pragma unroll
        for (int nt = 0; nt < 2; nt++) {
            const int px0 = pb + nt * 8;
            float c0 = bl, c1 = bl, c2 = bh, c3 = bh;
            #pragma unroll
            for (int kt = 0; kt < 4; kt++) {
                int k0 = kt * 8;
                uint32_t bv0 = __float_as_uint(h2s[(k0 + t) * YP + px0 + g]);
                uint32_t bv1 = __float_as_uint(h2s[(k0 + t + 4) * YP + px0 + g]);
                mma_tf32(c0, c1, c2, c3, A[kt][0], A[kt][1], A[kt][2], A[kt][3], bv0, bv1);
            }
            dxT[(px0 + 2 * t) * DP + g]         = c0;
            dxT[(px0 + 2 * t + 1) * DP + g]     = c1;
            dxT[(px0 + 2 * t) * DP + g + 8]     = c2;
            dxT[(px0 + 2 * t + 1) * DP + g + 8] = c3;
        }
    }
    __syncthreads();

    // ---------------- phase 5: out = x + dx*mask ----------------
    {
        const int px = tid >> 1;          // 0..127
        const int c0 = (tid & 1) * 8;     // channel half
        const int py = px >> 4, xx = px & 15;
        const float m = ms[px];
        const float* d = dxT + px * DP + c0;
        const int hbase = (py + 1) * 18 + (xx + 1);
        float* o = out + (((size_t)bb * HW + (y0 + py)) * HW + (x0 + xx)) * CH + c0;
        float4 r0, r1;
        r0.x = xs[(c0 + 0) * XCS + hbase] + d[0] * m;
        r0.y = xs[(c0 + 1) * XCS + hbase] + d[1] * m;
        r0.z = xs[(c0 + 2) * XCS + hbase] + d[2] * m;
        r0.w = xs[(c0 + 3) * XCS + hbase] + d[3] * m;
        r1.x = xs[(c0 + 4) * XCS + hbase] + d[4] * m;
        r1.y = xs[(c0 + 5) * XCS + hbase] + d[5] * m;
        r1.z = xs[(c0 + 6) * XCS + hbase] + d[6] * m;
        r1.w = xs[(c0 + 7) * XCS + hbase] + d[7] * m;
        *(float4*)&o[0] = r0;
        *(float4*)&o[4] = r1;
    }
}

extern "C" void kernel_launch(void* const* d_in, const int* in_sizes, int n_in,
                              void* d_out, int out_size)
{
    const float* x  = (const float*)d_in[0];
    const float* w1 = (const float*)d_in[1];
    const float* b1 = (const float*)d_in[2];
    const float* w2 = (const float*)d_in[3];
    const float* b2 = (const float*)d_in[4];
    const float* w3 = (const float*)d_in[5];
    const float* b3 = (const float*)d_in[6];
    const uint32_t* mask = (const uint32_t*)d_in[7];
    float* out = (float*)d_out;

    cudaFuncSetAttribute(nca_step_kernel,
                         cudaFuncAttributeMaxDynamicSharedMemorySize, SMEM_BYTES);
    dim3 grid(HW / TW, HW / TH, 16);
    nca_step_kernel<<<grid, 256, SMEM_BYTES>>>(x, w1, b1, w2, b2, w3, b3, mask, out);
}